// round 1
// baseline (speedup 1.0000x reference)
#include <cuda_runtime.h>

// Problem constants
#define Bb 8
#define Mm 2048
#define NN 2048
#define Dd 128

#define BM 64
#define BN 64
#define TPB 256

#define SCALE_F 0.5f
#define KEEP_F 0.8f
#define INV_KEEP_F 1.25f

// ---------------------------------------------------------------------------
// JAX threefry2x32, partitionable path:
//   key = threefry_seed(42) = (0, 42)
//   counter = (hi, lo) of 64-bit flat index; hi == 0 for size < 2^32
//   bits = out0 ^ out1 ; u = bitcast(bits>>9 | 0x3f800000) - 1.0 ; keep = u < 0.8
// ---------------------------------------------------------------------------
__device__ __forceinline__ float tf_uniform(unsigned ctr)
{
    const unsigned K0 = 0u;
    const unsigned K1 = 42u;
    const unsigned K2 = 0x1BD11BDAu ^ 0u ^ 42u;  // 0x1BD11BF0

    unsigned x0 = 0u  + K0;   // hi counter = 0
    unsigned x1 = ctr + K1;   // lo counter = flat index

#define TF_RND(r) { x0 += x1; x1 = __funnelshift_l(x1, x1, (r)); x1 ^= x0; }
    TF_RND(13) TF_RND(15) TF_RND(26) TF_RND(6)
    x0 += K1; x1 += K2 + 1u;
    TF_RND(17) TF_RND(29) TF_RND(16) TF_RND(24)
    x0 += K2; x1 += K0 + 2u;
    TF_RND(13) TF_RND(15) TF_RND(26) TF_RND(6)
    x0 += K0; x1 += K1 + 3u;
    TF_RND(17) TF_RND(29) TF_RND(16) TF_RND(24)
    x0 += K1; x1 += K2 + 4u;
    TF_RND(13) TF_RND(15) TF_RND(26) TF_RND(6)
    x0 += K2; x1 += K0 + 5u;
#undef TF_RND

    unsigned bits = x0 ^ x1;
    return __uint_as_float((bits >> 9) | 0x3f800000u) - 1.0f;
}

// ---------------------------------------------------------------------------
// Fused flash attention (fp32, SIMT) with exact-match JAX dropout.
// Grid: (M/BM, B). Block: 256 threads = 16x16.
// Thread (ty,tx): S microtile rows ty*4..+3, cols tx*4..+3
//                 O microtile rows ty*4..+3, d-cols tx*8..+7
// ---------------------------------------------------------------------------
__global__ void __launch_bounds__(TPB, 2)
attn_kernel(const float* __restrict__ x1,
            const float* __restrict__ x2,
            float* __restrict__ out)
{
    extern __shared__ float smem[];
    float* sQ = smem;                 // BM * Dd
    float* sK = sQ + BM * Dd;         // BN * Dd   (K and V are the same tile)
    float* sP = sK + BN * Dd;         // BM * BN

    const int b  = blockIdx.y;
    const int m0 = blockIdx.x * BM;
    const int tid = threadIdx.x;
    const int ty = tid >> 4;
    const int tx = tid & 15;

    // Load Q tile: BM*Dd contiguous floats
    {
        const float4* gQ = (const float4*)(x1 + ((size_t)b * Mm + m0) * Dd);
        float4* dQ = (float4*)sQ;
        #pragma unroll
        for (int idx = tid; idx < BM * Dd / 4; idx += TPB)
            dQ[idx] = gQ[idx];
    }

    float mrow[4], lrow[4];
    float o[4][8];
    #pragma unroll
    for (int i = 0; i < 4; i++) {
        mrow[i] = -1e30f;
        lrow[i] = 0.0f;
        #pragma unroll
        for (int j = 0; j < 8; j++) o[i][j] = 0.0f;
    }

    const float* qbase = sQ + (ty * 4) * Dd;
    const float* kbase = sK + (tx * 4) * Dd;

    for (int n0 = 0; n0 < NN; n0 += BN) {
        __syncthreads();   // protect sK/sP from previous iteration's readers
        {
            const float4* gK = (const float4*)(x2 + ((size_t)b * NN + n0) * Dd);
            float4* dK = (float4*)sK;
            #pragma unroll
            for (int idx = tid; idx < BN * Dd / 4; idx += TPB)
                dK[idx] = gK[idx];
        }
        __syncthreads();

        // ---- S = (Q K^T) * 0.5, 4x4 microtile ----
        float acc[4][4];
        #pragma unroll
        for (int i = 0; i < 4; i++)
            #pragma unroll
            for (int j = 0; j < 4; j++) acc[i][j] = 0.0f;

        #pragma unroll 8
        for (int d = 0; d < Dd; d += 4) {
            float4 q[4], k[4];
            #pragma unroll
            for (int i = 0; i < 4; i++) q[i] = *(const float4*)(qbase + i * Dd + d);
            #pragma unroll
            for (int j = 0; j < 4; j++) k[j] = *(const float4*)(kbase + j * Dd + d);
            #pragma unroll
            for (int i = 0; i < 4; i++)
                #pragma unroll
                for (int j = 0; j < 4; j++) {
                    acc[i][j] = fmaf(q[i].x, k[j].x, acc[i][j]);
                    acc[i][j] = fmaf(q[i].y, k[j].y, acc[i][j]);
                    acc[i][j] = fmaf(q[i].z, k[j].z, acc[i][j]);
                    acc[i][j] = fmaf(q[i].w, k[j].w, acc[i][j]);
                }
        }

        // ---- online softmax + dropout, P -> smem ----
        #pragma unroll
        for (int i = 0; i < 4; i++) {
            float s0 = acc[i][0] * SCALE_F;
            float s1 = acc[i][1] * SCALE_F;
            float s2 = acc[i][2] * SCALE_F;
            float s3 = acc[i][3] * SCALE_F;

            float tmax = fmaxf(fmaxf(s0, s1), fmaxf(s2, s3));
            #pragma unroll
            for (int off = 1; off < 16; off <<= 1)
                tmax = fmaxf(tmax, __shfl_xor_sync(0xffffffffu, tmax, off));

            float mnew  = fmaxf(mrow[i], tmax);
            float alpha = __expf(mrow[i] - mnew);

            float p0 = __expf(s0 - mnew);
            float p1 = __expf(s1 - mnew);
            float p2 = __expf(s2 - mnew);
            float p3 = __expf(s3 - mnew);

            float tsum = (p0 + p1) + (p2 + p3);
            #pragma unroll
            for (int off = 1; off < 16; off <<= 1)
                tsum += __shfl_xor_sync(0xffffffffu, tsum, off);

            lrow[i] = lrow[i] * alpha + tsum;
            mrow[i] = mnew;
            #pragma unroll
            for (int j = 0; j < 8; j++) o[i][j] *= alpha;

            // dropout mask: flat index into (B, M, N)
            unsigned base = ((unsigned)(b * Mm + m0 + ty * 4 + i)) * (unsigned)NN
                          + (unsigned)(n0 + tx * 4);
            float pm0 = (tf_uniform(base + 0u) < KEEP_F) ? p0 * INV_KEEP_F : 0.0f;
            float pm1 = (tf_uniform(base + 1u) < KEEP_F) ? p1 * INV_KEEP_F : 0.0f;
            float pm2 = (tf_uniform(base + 2u) < KEEP_F) ? p2 * INV_KEEP_F : 0.0f;
            float pm3 = (tf_uniform(base + 3u) < KEEP_F) ? p3 * INV_KEEP_F : 0.0f;

            *(float4*)(sP + (ty * 4 + i) * BN + tx * 4) = make_float4(pm0, pm1, pm2, pm3);
        }
        __syncthreads();

        // ---- O += P * V  (V = sK tile) ----
        const float* vb = sK + tx * 8;
        #pragma unroll 4
        for (int c = 0; c < BN; c++) {
            float4 v0 = *(const float4*)(vb + c * Dd);
            float4 v1 = *(const float4*)(vb + c * Dd + 4);
            #pragma unroll
            for (int i = 0; i < 4; i++) {
                float p = sP[(ty * 4 + i) * BN + c];
                o[i][0] = fmaf(p, v0.x, o[i][0]);
                o[i][1] = fmaf(p, v0.y, o[i][1]);
                o[i][2] = fmaf(p, v0.z, o[i][2]);
                o[i][3] = fmaf(p, v0.w, o[i][3]);
                o[i][4] = fmaf(p, v1.x, o[i][4]);
                o[i][5] = fmaf(p, v1.y, o[i][5]);
                o[i][6] = fmaf(p, v1.z, o[i][6]);
                o[i][7] = fmaf(p, v1.w, o[i][7]);
            }
        }
    }

    // ---- write out: out[b, m, d] = o / l ----
    #pragma unroll
    for (int i = 0; i < 4; i++) {
        float inv = 1.0f / lrow[i];
        float* gO = out + ((size_t)b * Mm + m0 + ty * 4 + i) * Dd + tx * 8;
        float4 a0 = make_float4(o[i][0] * inv, o[i][1] * inv, o[i][2] * inv, o[i][3] * inv);
        float4 a1 = make_float4(o[i][4] * inv, o[i][5] * inv, o[i][6] * inv, o[i][7] * inv);
        *(float4*)(gO)     = a0;
        *(float4*)(gO + 4) = a1;
    }
}

extern "C" void kernel_launch(void* const* d_in, const int* in_sizes, int n_in,
                              void* d_out, int out_size)
{
    const float* x1 = (const float*)d_in[0];
    const float* x2 = (const float*)d_in[1];
    float* out = (float*)d_out;

    const int smem_bytes = (BM * Dd + BN * Dd + BM * BN) * (int)sizeof(float); // 81920
    cudaFuncSetAttribute(attn_kernel, cudaFuncAttributeMaxDynamicSharedMemorySize, smem_bytes);

    dim3 grid(Mm / BM, Bb);
    attn_kernel<<<grid, TPB, smem_bytes>>>(x1, x2, out);
}

// round 2
// speedup vs baseline: 2.6152x; 2.6152x over previous
#include <cuda_runtime.h>

#define Bb 8
#define Mm 2048
#define NN 2048
#define Dd 128
#define BM 64
#define BN 64
#define TPB 256
#define NTILE 32

#define SCALE_F 0.5f
#define KEEP_F 0.8f
#define INV_KEEP_F 1.25f

typedef unsigned long long u64;
typedef ulonglong2 u64x2;

// ---- packed f32x2 helpers (Blackwell FFMA2) ----
__device__ __forceinline__ u64 fma2(u64 a, u64 b, u64 c){
    u64 d; asm("fma.rn.f32x2 %0, %1, %2, %3;" : "=l"(d) : "l"(a), "l"(b), "l"(c));
    return d;
}
__device__ __forceinline__ u64 mul2(u64 a, u64 b){
    u64 d; asm("mul.rn.f32x2 %0, %1, %2;" : "=l"(d) : "l"(a), "l"(b));
    return d;
}
__device__ __forceinline__ u64 dup2(float x){
    unsigned u = __float_as_uint(x);
    u64 d; asm("mov.b64 %0, {%1, %2};" : "=l"(d) : "r"(u), "r"(u));
    return d;
}
__device__ __forceinline__ float2 unpk(u64 v){
    unsigned lo, hi;
    asm("mov.b64 {%0, %1}, %2;" : "=r"(lo), "=r"(hi) : "l"(v));
    return make_float2(__uint_as_float(lo), __uint_as_float(hi));
}

// ---------------------------------------------------------------------------
// JAX threefry2x32, partitionable path (verified exact in R1):
//   key=(0,42), counter=(0, flat_idx), bits = x0^x1, u = bits>>9 mapped to [0,1)
// ---------------------------------------------------------------------------
__device__ __forceinline__ float tf_uniform(unsigned ctr)
{
    const unsigned K0 = 0u;
    const unsigned K1 = 42u;
    const unsigned K2 = 0x1BD11BDAu ^ 0u ^ 42u;

    unsigned x0 = 0u  + K0;
    unsigned x1 = ctr + K1;

#define TF_RND(r) { x0 += x1; x1 = __funnelshift_l(x1, x1, (r)); x1 ^= x0; }
    TF_RND(13) TF_RND(15) TF_RND(26) TF_RND(6)
    x0 += K1; x1 += K2 + 1u;
    TF_RND(17) TF_RND(29) TF_RND(16) TF_RND(24)
    x0 += K2; x1 += K0 + 2u;
    TF_RND(13) TF_RND(15) TF_RND(26) TF_RND(6)
    x0 += K0; x1 += K1 + 3u;
    TF_RND(17) TF_RND(29) TF_RND(16) TF_RND(24)
    x0 += K1; x1 += K2 + 4u;
    TF_RND(13) TF_RND(15) TF_RND(26) TF_RND(6)
    x0 += K2; x1 += K0 + 5u;
#undef TF_RND

    unsigned bits = x0 ^ x1;
    return __uint_as_float((bits >> 9) | 0x3f800000u) - 1.0f;
}

// ---------------------------------------------------------------------------
// Async copy of a 64x128-float tile with XOR swizzle (float4 granularity):
// logical chunk c of row r is stored at chunk (c ^ ((r>>2)&7)).
// ---------------------------------------------------------------------------
__device__ __forceinline__ void copy_tile_async(float4* dst, const float4* gsrc, int tid){
    #pragma unroll
    for (int k = 0; k < 8; k++){
        int idx = tid + k * TPB;          // 0..2047
        int row = idx >> 5;
        int c   = idx & 31;
        int di  = (row << 5) | (c ^ ((row >> 2) & 7));
        unsigned daddr = (unsigned)__cvta_generic_to_shared(dst + di);
        asm volatile("cp.async.cg.shared.global [%0], [%1], 16;"
                     :: "r"(daddr), "l"(gsrc + idx));
    }
}

// ---------------------------------------------------------------------------
// Fused flash attention, fp32 via packed f32x2, swizzled smem, cp.async pipe.
// Grid (M/BM, B), block 256 = 16x16 threads, microtile 4x4.
// Thread (ty,tx): S rows 4ty..+3, S cols 4tx..+3;
//                 O rows 4ty..+3, O d-cols [4tx,4tx+4) and [64+4tx, 64+4tx+4)
// ---------------------------------------------------------------------------
__global__ void __launch_bounds__(TPB, 2)
attn_kernel(const float* __restrict__ x1,
            const float* __restrict__ x2,
            float* __restrict__ out)
{
    extern __shared__ float4 smem4[];
    float4* sQ  = smem4;            // 2048 float4
    float4* sKa = sQ  + 2048;       // K tile buffer 0
    float4* sKb = sKa + 2048;       // K tile buffer 1
    float*  sP  = (float*)(sKb + 2048);   // BM*BN floats

    const int b   = blockIdx.y;
    const int m0  = blockIdx.x * BM;
    const int tid = threadIdx.x;
    const int ty  = tid >> 4;
    const int tx  = tid & 15;

    const float4* gQ = (const float4*)(x1 + ((size_t)b * Mm + m0) * Dd);
    const float4* gK = (const float4*)(x2 + (size_t)b * NN * Dd);

    copy_tile_async(sQ,  gQ, tid);
    copy_tile_async(sKa, gK, tid);
    asm volatile("cp.async.commit_group;");

    float mrow[4], lrow[4];
    u64 oA[4][2], oB[4][2];
    #pragma unroll
    for (int i = 0; i < 4; i++){
        mrow[i] = -1e30f; lrow[i] = 0.0f;
        oA[i][0] = oA[i][1] = 0ull;
        oB[i][0] = oB[i][1] = 0ull;
    }

    const int sqk = (ty ^ tx) & 7;          // combined q/k swizzle for QK loop
    const float4* qbase = sQ + (4 * ty) * 32;

    for (int t = 0; t < NTILE; t++){
        float4* bufc = (t & 1) ? sKb : sKa;
        float4* bufn = (t & 1) ? sKa : sKb;
        if (t < NTILE - 1){
            copy_tile_async(bufn, gK + (size_t)(t + 1) * 2048, tid);
            asm volatile("cp.async.commit_group;");
        }

        // ---- dropout mask for this tile (ALU work overlaps copy latency) ----
        unsigned mask = 0;
        #pragma unroll 1
        for (int i = 0; i < 4; i++){
            unsigned base = (unsigned)(b * Mm + m0 + 4 * ty + i) * (unsigned)NN
                          + (unsigned)(t * BN + 4 * tx);
            unsigned mb = 0;
            if (tf_uniform(base + 0u) < KEEP_F) mb |= 1u;
            if (tf_uniform(base + 1u) < KEEP_F) mb |= 2u;
            if (tf_uniform(base + 2u) < KEEP_F) mb |= 4u;
            if (tf_uniform(base + 3u) < KEEP_F) mb |= 8u;
            mask |= mb << (i * 4);
        }

        if (t < NTILE - 1) { asm volatile("cp.async.wait_group 1;" ::: "memory"); }
        else               { asm volatile("cp.async.wait_group 0;" ::: "memory"); }
        __syncthreads();

        // ---- S = (Q K^T), packed pairs along d ----
        u64 acc[4][4];
        #pragma unroll
        for (int i = 0; i < 4; i++)
            #pragma unroll
            for (int j = 0; j < 4; j++) acc[i][j] = 0ull;

        const float4* kbase = bufc + (4 * tx) * 32;
        #pragma unroll 4
        for (int v = 0; v < 32; v++){           // v = stored q-chunk index
            const int kc = v ^ sqk;             // matching stored k-chunk
            u64x2 q[4], k[4];
            #pragma unroll
            for (int i = 0; i < 4; i++)
                q[i] = *(const u64x2*)(qbase + i * 32 + v);
            #pragma unroll
            for (int j = 0; j < 4; j++)
                k[j] = *(const u64x2*)(kbase + j * 32 + kc);
            #pragma unroll
            for (int i = 0; i < 4; i++)
                #pragma unroll
                for (int j = 0; j < 4; j++){
                    acc[i][j] = fma2(q[i].x, k[j].x, acc[i][j]);
                    acc[i][j] = fma2(q[i].y, k[j].y, acc[i][j]);
                }
        }

        // ---- online softmax + dropout, P -> smem ----
        #pragma unroll
        for (int i = 0; i < 4; i++){
            float2 a0 = unpk(acc[i][0]);
            float2 a1 = unpk(acc[i][1]);
            float2 a2 = unpk(acc[i][2]);
            float2 a3 = unpk(acc[i][3]);
            float s0 = (a0.x + a0.y) * SCALE_F;
            float s1 = (a1.x + a1.y) * SCALE_F;
            float s2 = (a2.x + a2.y) * SCALE_F;
            float s3 = (a3.x + a3.y) * SCALE_F;

            float tmax = fmaxf(fmaxf(s0, s1), fmaxf(s2, s3));
            #pragma unroll
            for (int off = 1; off < 16; off <<= 1)
                tmax = fmaxf(tmax, __shfl_xor_sync(0xffffffffu, tmax, off));

            float mnew  = fmaxf(mrow[i], tmax);
            float alpha = __expf(mrow[i] - mnew);

            float p0 = __expf(s0 - mnew);
            float p1 = __expf(s1 - mnew);
            float p2 = __expf(s2 - mnew);
            float p3 = __expf(s3 - mnew);

            float tsum = (p0 + p1) + (p2 + p3);
            #pragma unroll
            for (int off = 1; off < 16; off <<= 1)
                tsum += __shfl_xor_sync(0xffffffffu, tsum, off);

            lrow[i] = lrow[i] * alpha + tsum;
            mrow[i] = mnew;

            u64 am = dup2(alpha);
            oA[i][0] = mul2(oA[i][0], am);
            oA[i][1] = mul2(oA[i][1], am);
            oB[i][0] = mul2(oB[i][0], am);
            oB[i][1] = mul2(oB[i][1], am);

            const unsigned mb = mask >> (i * 4);
            float pm0 = (mb & 1u) ? p0 * INV_KEEP_F : 0.0f;
            float pm1 = (mb & 2u) ? p1 * INV_KEEP_F : 0.0f;
            float pm2 = (mb & 4u) ? p2 * INV_KEEP_F : 0.0f;
            float pm3 = (mb & 8u) ? p3 * INV_KEEP_F : 0.0f;

            *(float4*)(sP + (4 * ty + i) * BN + 4 * tx) = make_float4(pm0, pm1, pm2, pm3);
        }
        __syncthreads();

        // ---- O += P * V (V = current K tile), packed pairs along d ----
        #pragma unroll 2
        for (int c0 = 0; c0 < BN; c0 += 4){
            float4 p4[4];
            #pragma unroll
            for (int i = 0; i < 4; i++)
                p4[i] = *(const float4*)(sP + (4 * ty + i) * BN + c0);

            const int s  = (c0 >> 2) & 7;      // row-group swizzle, const over cc
            const int ia = tx ^ s;
            const int ib = 16 + ia;
            #pragma unroll
            for (int cc = 0; cc < 4; cc++){
                const float4* vrow = bufc + (c0 + cc) * 32;
                u64x2 va = *(const u64x2*)(vrow + ia);
                u64x2 vb = *(const u64x2*)(vrow + ib);
                #pragma unroll
                for (int i = 0; i < 4; i++){
                    float pv = ((const float*)&p4[i])[cc];
                    u64 pd = dup2(pv);
                    oA[i][0] = fma2(pd, va.x, oA[i][0]);
                    oA[i][1] = fma2(pd, va.y, oA[i][1]);
                    oB[i][0] = fma2(pd, vb.x, oB[i][0]);
                    oB[i][1] = fma2(pd, vb.y, oB[i][1]);
                }
            }
        }
        __syncthreads();   // buf[cur] fully consumed before it becomes a prefetch target
    }

    // ---- epilogue: out = o / l ----
    #pragma unroll
    for (int i = 0; i < 4; i++){
        u64 iv = dup2(1.0f / lrow[i]);
        float2 r0 = unpk(mul2(oA[i][0], iv));
        float2 r1 = unpk(mul2(oA[i][1], iv));
        float2 r2 = unpk(mul2(oB[i][0], iv));
        float2 r3 = unpk(mul2(oB[i][1], iv));
        float* gO = out + ((size_t)b * Mm + m0 + 4 * ty + i) * Dd;
        *(float4*)(gO + 4 * tx)      = make_float4(r0.x, r0.y, r1.x, r1.y);
        *(float4*)(gO + 64 + 4 * tx) = make_float4(r2.x, r2.y, r3.x, r3.y);
    }
}

extern "C" void kernel_launch(void* const* d_in, const int* in_sizes, int n_in,
                              void* d_out, int out_size)
{
    const float* x1 = (const float*)d_in[0];
    const float* x2 = (const float*)d_in[1];
    float* out = (float*)d_out;

    // smem: Q (32KB) + 2x K (64KB) + P (16KB) = 112KB -> 2 CTAs/SM
    const int smem_bytes = 3 * 2048 * (int)sizeof(float4) + BM * BN * (int)sizeof(float);
    cudaFuncSetAttribute(attn_kernel, cudaFuncAttributeMaxDynamicSharedMemorySize, smem_bytes);

    dim3 grid(Mm / BM, Bb);
    attn_kernel<<<grid, TPB, smem_bytes>>>(x1, x2, out);
}

// round 3
// speedup vs baseline: 2.6609x; 1.0175x over previous
#include <cuda_runtime.h>

#define Bb 8
#define Mm 2048
#define NN 2048
#define Dd 128
#define BM 64
#define BN 64
#define TPB 256
#define NTILE 32

#define KEEP_F 0.8f
#define INV_KEEP_F 1.25f
// 0.5 (score scale) * log2(e), folded so probs = exp2(dot * C2)
#define C2 0.7213475204444817f

typedef unsigned long long u64;
typedef ulonglong2 u64x2;

// ---- packed f32x2 helpers (Blackwell FFMA2) ----
__device__ __forceinline__ u64 fma2(u64 a, u64 b, u64 c){
    u64 d; asm("fma.rn.f32x2 %0, %1, %2, %3;" : "=l"(d) : "l"(a), "l"(b), "l"(c));
    return d;
}
__device__ __forceinline__ u64 mul2(u64 a, u64 b){
    u64 d; asm("mul.rn.f32x2 %0, %1, %2;" : "=l"(d) : "l"(a), "l"(b));
    return d;
}
__device__ __forceinline__ u64 dup2(float x){
    unsigned u = __float_as_uint(x);
    u64 d; asm("mov.b64 %0, {%1, %2};" : "=l"(d) : "r"(u), "r"(u));
    return d;
}
__device__ __forceinline__ float2 unpk(u64 v){
    unsigned lo, hi;
    asm("mov.b64 {%0, %1}, %2;" : "=r"(lo), "=r"(hi) : "l"(v));
    return make_float2(__uint_as_float(lo), __uint_as_float(hi));
}

// ---------------------------------------------------------------------------
// JAX threefry2x32, partitionable path (bit-exact verified in R1/R2 — frozen):
//   key=(0,42), counter=(0, flat_idx), bits = x0^x1, u = bits>>9 mapped to [0,1)
// ---------------------------------------------------------------------------
__device__ __forceinline__ float tf_uniform(unsigned ctr)
{
    const unsigned K0 = 0u;
    const unsigned K1 = 42u;
    const unsigned K2 = 0x1BD11BDAu ^ 0u ^ 42u;

    unsigned x0 = 0u  + K0;
    unsigned x1 = ctr + K1;

#define TF_RND(r) { x0 += x1; x1 = __funnelshift_l(x1, x1, (r)); x1 ^= x0; }
    TF_RND(13) TF_RND(15) TF_RND(26) TF_RND(6)
    x0 += K1; x1 += K2 + 1u;
    TF_RND(17) TF_RND(29) TF_RND(16) TF_RND(24)
    x0 += K2; x1 += K0 + 2u;
    TF_RND(13) TF_RND(15) TF_RND(26) TF_RND(6)
    x0 += K0; x1 += K1 + 3u;
    TF_RND(17) TF_RND(29) TF_RND(16) TF_RND(24)
    x0 += K1; x1 += K2 + 4u;
    TF_RND(13) TF_RND(15) TF_RND(26) TF_RND(6)
    x0 += K2; x1 += K0 + 5u;
#undef TF_RND

    unsigned bits = x0 ^ x1;
    return __uint_as_float((bits >> 9) | 0x3f800000u) - 1.0f;
}

// ---------------------------------------------------------------------------
// Async copy of a 64x128-float tile with XOR swizzle (float4 granularity):
// logical chunk c of row r is stored at chunk (c ^ ((r>>2)&7)).
// ---------------------------------------------------------------------------
__device__ __forceinline__ void copy_tile_async(float4* dst, const float4* gsrc, int tid){
    #pragma unroll
    for (int k = 0; k < 8; k++){
        int idx = tid + k * TPB;          // 0..2047
        int row = idx >> 5;
        int c   = idx & 31;
        int di  = (row << 5) | (c ^ ((row >> 2) & 7));
        unsigned daddr = (unsigned)__cvta_generic_to_shared(dst + di);
        asm volatile("cp.async.cg.shared.global [%0], [%1], 16;"
                     :: "r"(daddr), "l"(gsrc + idx));
    }
}

// ---------------------------------------------------------------------------
// Fused attention, fp32 via packed f32x2, swizzled smem, cp.async pipeline.
// No-max softmax: probs = exp2(dot * C2); denominators deferred to epilogue.
// Grid (M/BM, B), block 256 = 16x16 threads, microtile 4x4.
// ---------------------------------------------------------------------------
__global__ void __launch_bounds__(TPB, 2)
attn_kernel(const float* __restrict__ x1,
            const float* __restrict__ x2,
            float* __restrict__ out)
{
    extern __shared__ float4 smem4[];
    float4* sQ  = smem4;            // 2048 float4
    float4* sKa = sQ  + 2048;       // K tile buffer 0
    float4* sKb = sKa + 2048;       // K tile buffer 1
    float*  sP  = (float*)(sKb + 2048);   // BM*BN floats

    const int b   = blockIdx.y;
    const int m0  = blockIdx.x * BM;
    const int tid = threadIdx.x;
    const int ty  = tid >> 4;
    const int tx  = tid & 15;

    const float4* gQ = (const float4*)(x1 + ((size_t)b * Mm + m0) * Dd);
    const float4* gK = (const float4*)(x2 + (size_t)b * NN * Dd);

    copy_tile_async(sQ,  gQ, tid);
    copy_tile_async(sKa, gK, tid);
    asm volatile("cp.async.commit_group;");

    float lrow[4];                  // per-thread partial sum of exp (pre-dropout)
    u64 oA[4][2], oB[4][2];
    #pragma unroll
    for (int i = 0; i < 4; i++){
        lrow[i] = 0.0f;
        oA[i][0] = oA[i][1] = 0ull;
        oB[i][0] = oB[i][1] = 0ull;
    }

    const int sqk = (ty ^ tx) & 7;          // combined q/k swizzle for QK loop
    const float4* qbase = sQ + (4 * ty) * 32;

    for (int t = 0; t < NTILE; t++){
        float4* bufc = (t & 1) ? sKb : sKa;
        float4* bufn = (t & 1) ? sKa : sKb;
        if (t < NTILE - 1){
            copy_tile_async(bufn, gK + (size_t)(t + 1) * 2048, tid);
            asm volatile("cp.async.commit_group;");
        }

        // ---- dropout mask for this tile (ALU work overlaps copy latency) ----
        unsigned mask = 0;
        #pragma unroll 1
        for (int i = 0; i < 4; i++){
            unsigned base = (unsigned)(b * Mm + m0 + 4 * ty + i) * (unsigned)NN
                          + (unsigned)(t * BN + 4 * tx);
            unsigned mb = 0;
            if (tf_uniform(base + 0u) < KEEP_F) mb |= 1u;
            if (tf_uniform(base + 1u) < KEEP_F) mb |= 2u;
            if (tf_uniform(base + 2u) < KEEP_F) mb |= 4u;
            if (tf_uniform(base + 3u) < KEEP_F) mb |= 8u;
            mask |= mb << (i * 4);
        }

        if (t < NTILE - 1) { asm volatile("cp.async.wait_group 1;" ::: "memory"); }
        else               { asm volatile("cp.async.wait_group 0;" ::: "memory"); }
        __syncthreads();

        // ---- S = (Q K^T), packed pairs along d ----
        u64 acc[4][4];
        #pragma unroll
        for (int i = 0; i < 4; i++)
            #pragma unroll
            for (int j = 0; j < 4; j++) acc[i][j] = 0ull;

        const float4* kbase = bufc + (4 * tx) * 32;
        #pragma unroll 4
        for (int v = 0; v < 32; v++){           // v = stored q-chunk index
            const int kc = v ^ sqk;             // matching stored k-chunk
            u64x2 q[4], k[4];
            #pragma unroll
            for (int i = 0; i < 4; i++)
                q[i] = *(const u64x2*)(qbase + i * 32 + v);
            #pragma unroll
            for (int j = 0; j < 4; j++)
                k[j] = *(const u64x2*)(kbase + j * 32 + kc);
            #pragma unroll
            for (int i = 0; i < 4; i++)
                #pragma unroll
                for (int j = 0; j < 4; j++){
                    acc[i][j] = fma2(q[i].x, k[j].x, acc[i][j]);
                    acc[i][j] = fma2(q[i].y, k[j].y, acc[i][j]);
                }
        }

        // ---- exp + dropout, P -> smem (no max, no rescale, no per-tile shfl) ----
        #pragma unroll
        for (int i = 0; i < 4; i++){
            float2 a0 = unpk(acc[i][0]);
            float2 a1 = unpk(acc[i][1]);
            float2 a2 = unpk(acc[i][2]);
            float2 a3 = unpk(acc[i][3]);

            float p0 = exp2f((a0.x + a0.y) * C2);
            float p1 = exp2f((a1.x + a1.y) * C2);
            float p2 = exp2f((a2.x + a2.y) * C2);
            float p3 = exp2f((a3.x + a3.y) * C2);

            lrow[i] += (p0 + p1) + (p2 + p3);   // denominator: pre-dropout sum

            const unsigned mb = mask >> (i * 4);
            float pm0 = (mb & 1u) ? p0 * INV_KEEP_F : 0.0f;
            float pm1 = (mb & 2u) ? p1 * INV_KEEP_F : 0.0f;
            float pm2 = (mb & 4u) ? p2 * INV_KEEP_F : 0.0f;
            float pm3 = (mb & 8u) ? p3 * INV_KEEP_F : 0.0f;

            *(float4*)(sP + (4 * ty + i) * BN + 4 * tx) = make_float4(pm0, pm1, pm2, pm3);
        }
        __syncthreads();

        // ---- O += P * V (V = current K tile), packed pairs along d ----
        #pragma unroll 2
        for (int c0 = 0; c0 < BN; c0 += 4){
            float4 p4[4];
            #pragma unroll
            for (int i = 0; i < 4; i++)
                p4[i] = *(const float4*)(sP + (4 * ty + i) * BN + c0);

            const int s  = (c0 >> 2) & 7;      // row-group swizzle, const over cc
            const int ia = tx ^ s;
            const int ib = 16 + ia;
            #pragma unroll
            for (int cc = 0; cc < 4; cc++){
                const float4* vrow = bufc + (c0 + cc) * 32;
                u64x2 va = *(const u64x2*)(vrow + ia);
                u64x2 vb = *(const u64x2*)(vrow + ib);
                #pragma unroll
                for (int i = 0; i < 4; i++){
                    float pv = ((const float*)&p4[i])[cc];
                    u64 pd = dup2(pv);
                    oA[i][0] = fma2(pd, va.x, oA[i][0]);
                    oA[i][1] = fma2(pd, va.y, oA[i][1]);
                    oB[i][0] = fma2(pd, vb.x, oB[i][0]);
                    oB[i][1] = fma2(pd, vb.y, oB[i][1]);
                }
            }
        }
        __syncthreads();   // buf[cur] fully consumed before it becomes a prefetch target
    }

    // ---- epilogue: one row-sum reduction per row, then out = o / l ----
    #pragma unroll
    for (int i = 0; i < 4; i++){
        float lsum = lrow[i];
        #pragma unroll
        for (int off = 1; off < 16; off <<= 1)
            lsum += __shfl_xor_sync(0xffffffffu, lsum, off);

        u64 iv = dup2(1.0f / lsum);
        float2 r0 = unpk(mul2(oA[i][0], iv));
        float2 r1 = unpk(mul2(oA[i][1], iv));
        float2 r2 = unpk(mul2(oB[i][0], iv));
        float2 r3 = unpk(mul2(oB[i][1], iv));
        float* gO = out + ((size_t)b * Mm + m0 + 4 * ty + i) * Dd;
        *(float4*)(gO + 4 * tx)      = make_float4(r0.x, r0.y, r1.x, r1.y);
        *(float4*)(gO + 64 + 4 * tx) = make_float4(r2.x, r2.y, r3.x, r3.y);
    }
}

extern "C" void kernel_launch(void* const* d_in, const int* in_sizes, int n_in,
                              void* d_out, int out_size)
{
    const float* x1 = (const float*)d_in[0];
    const float* x2 = (const float*)d_in[1];
    float* out = (float*)d_out;

    // smem: Q (32KB) + 2x K (64KB) + P (16KB) = 112KB -> 2 CTAs/SM
    const int smem_bytes = 3 * 2048 * (int)sizeof(float4) + BM * BN * (int)sizeof(float);
    cudaFuncSetAttribute(attn_kernel, cudaFuncAttributeMaxDynamicSharedMemorySize, smem_bytes);

    dim3 grid(Mm / BM, Bb);
    attn_kernel<<<grid, TPB, smem_bytes>>>(x1, x2, out);
}

// round 5
// speedup vs baseline: 5.7281x; 2.1527x over previous
#include <cuda_runtime.h>
#include <cstdint>

typedef uint32_t u32;

#define Bb 8
#define Mm 2048
#define NNs 2048
#define Dd 128
#define BM 128
#define BN 64
#define TPB 256
#define NT 32

#define C2 0.7213475204444817f   /* 0.5 * log2(e) */
#define INV_KEEP 1.25f

// ---- smem layout (bytes). bf16 tiles: 256B rows; staging: 512B rows ----
#define OF_QH 0         /* 128x128 bf16 hi = 32KB */
#define OF_QL 32768
#define OF_KH 65536     /* 64x128 bf16 hi = 16KB */
#define OF_KL 81920
#define OF_S0 98304     /* fp32 K staging, 32KB each */
#define OF_S1 131072
#define SMEM_TOTAL 163840

// swizzled byte address inside a 256B-row bf16 tile
__device__ __forceinline__ u32 swa(u32 base, int row, int colb){
    return base + (u32)(row * 256) + (u32)((((colb >> 4) ^ (row & 7)) << 4) + (colb & 15));
}

__device__ __forceinline__ void ldsm4(u32* r, u32 a){
    asm volatile("ldmatrix.sync.aligned.m8n8.x4.shared.b16 {%0,%1,%2,%3},[%4];"
        : "=r"(r[0]),"=r"(r[1]),"=r"(r[2]),"=r"(r[3]) : "r"(a));
}
__device__ __forceinline__ void ldsm4t(u32* r, u32 a){
    asm volatile("ldmatrix.sync.aligned.m8n8.x4.trans.shared.b16 {%0,%1,%2,%3},[%4];"
        : "=r"(r[0]),"=r"(r[1]),"=r"(r[2]),"=r"(r[3]) : "r"(a));
}
__device__ __forceinline__ void mmabf(float* c, const u32* a, u32 b0, u32 b1){
    asm volatile("mma.sync.aligned.m16n8k16.row.col.f32.bf16.bf16.f32 "
        "{%0,%1,%2,%3},{%4,%5,%6,%7},{%8,%9},{%0,%1,%2,%3};"
        : "+f"(c[0]),"+f"(c[1]),"+f"(c[2]),"+f"(c[3])
        : "r"(a[0]),"r"(a[1]),"r"(a[2]),"r"(a[3]),"r"(b0),"r"(b1));
}

// fp32 pair -> packed bf16 hi pair + lo pair (lo = x - bf16(x))
__device__ __forceinline__ void split_pair(float p0, float p1, u32& h2, u32& l2){
    asm("cvt.rn.bf16x2.f32 %0, %1, %2;" : "=r"(h2) : "f"(p1), "f"(p0));
    float h0 = __uint_as_float(h2 << 16);
    float h1 = __uint_as_float(h2 & 0xffff0000u);
    float r0 = p0 - h0, r1 = p1 - h1;
    asm("cvt.rn.bf16x2.f32 %0, %1, %2;" : "=r"(l2) : "f"(r1), "f"(r0));
}
__device__ __forceinline__ u32 pack_bf16(float p0, float p1){
    u32 h; asm("cvt.rn.bf16x2.f32 %0, %1, %2;" : "=r"(h) : "f"(p1), "f"(p0));
    return h;
}
__device__ __forceinline__ float ex2f(float x){
    float r; asm("ex2.approx.f32 %0, %1;" : "=f"(r) : "f"(x)); return r;
}

// JAX threefry2x32 partitionable, bit-exact (frozen since R1).
// keep <=> (bits>>9) <= 6710886  (u < 0.8f)
__device__ __forceinline__ u32 tf_keep(u32 ctr)
{
    const u32 K1 = 42u;
    const u32 K2 = 0x1BD11BDAu ^ 42u;
    u32 x0 = 0u;
    u32 x1 = ctr + K1;
#define TF_RND(r) { x0 += x1; x1 = __funnelshift_l(x1, x1, (r)); x1 ^= x0; }
    TF_RND(13) TF_RND(15) TF_RND(26) TF_RND(6)
    x0 += K1; x1 += K2 + 1u;
    TF_RND(17) TF_RND(29) TF_RND(16) TF_RND(24)
    x0 += K2; x1 += 0u + 2u;
    TF_RND(13) TF_RND(15) TF_RND(26) TF_RND(6)
    x0 += 0u; x1 += K1 + 3u;
    TF_RND(17) TF_RND(29) TF_RND(16) TF_RND(24)
    x0 += K1; x1 += K2 + 4u;
    TF_RND(13) TF_RND(15) TF_RND(26) TF_RND(6)
    x0 += K2; x1 += 0u + 5u;
#undef TF_RND
    return (((x0 ^ x1) >> 9) <= 6710886u) ? 1u : 0u;
}

// cp.async a 64x128-fp32 K tile into swizzled staging (512B rows, 32 chunks)
__device__ __forceinline__ void cp_stage(u32 dstb, const float4* gsrc, int tid){
    #pragma unroll
    for (int k = 0; k < 8; k++){
        int idx = tid + k * TPB;
        int row = idx >> 5;
        int c   = idx & 31;
        u32 da = dstb + (u32)(row * 512) + (u32)((c ^ (row & 7)) << 4);
        asm volatile("cp.async.cg.shared.global [%0], [%1], 16;"
                     :: "r"(da), "l"(gsrc + idx));
    }
}

__global__ void __launch_bounds__(TPB, 1)
attn_hmma(const float* __restrict__ x1, const float* __restrict__ x2, float* __restrict__ out)
{
    extern __shared__ char sm[];
    const u32 smb = (u32)__cvta_generic_to_shared(sm);
    const int tid  = threadIdx.x;
    const int w    = tid >> 5;
    const int lane = tid & 31;
    const int gID  = lane >> 2;
    const int tig  = lane & 3;
    const int b    = blockIdx.y;
    const int mrow0 = blockIdx.x * BM;

    const u32 QH = smb + OF_QH, QL = smb + OF_QL;
    const u32 KH = smb + OF_KH, KL = smb + OF_KL;

    // prefetch K tile 0
    const float4* gK4 = (const float4*)(x2 + (size_t)b * NNs * Dd);
    cp_stage(smb + OF_S0, gK4, tid);
    asm volatile("cp.async.commit_group;");

    // ---- Q: fp32 load -> split bf16 hi/lo into swizzled smem (once) ----
    {
        int qrow = tid >> 1, qh = tid & 1;
        const float4* g = (const float4*)(x1 + ((size_t)b * Mm + mrow0 + qrow) * Dd + qh * 64);
        char* qhp = sm + OF_QH;
        char* qlp = sm + OF_QL;
        #pragma unroll
        for (int j = 0; j < 16; j++){
            float4 v = g[j];
            int d0 = qh * 64 + 4 * j;
            u32 h2, l2;
            int cb = 2 * d0;
            int a0 = qrow * 256 + (((cb >> 4) ^ (qrow & 7)) << 4) + (cb & 15);
            split_pair(v.x, v.y, h2, l2);
            *(u32*)(qhp + a0) = h2; *(u32*)(qlp + a0) = l2;
            split_pair(v.z, v.w, h2, l2);
            *(u32*)(qhp + a0 + 4) = h2; *(u32*)(qlp + a0 + 4) = l2;
        }
    }

    // per-lane ldmatrix row/col patterns
    const int r0  = w * 16;
    const int rA  = ((lane >> 3) & 1) * 8 + (lane & 7);   // A & PV-B(trans) pattern
    const int cA  = ((lane >> 4) & 1) * 16;
    const int rBq = ((lane >> 4) & 1) * 8 + (lane & 7);   // QK-B pattern
    const int cBq = ((lane >> 3) & 1) * 16;

    float o[16][4];
    #pragma unroll
    for (int i = 0; i < 16; i++){ o[i][0]=o[i][1]=o[i][2]=o[i][3]=0.f; }
    float lsum0 = 0.f, lsum1 = 0.f;

    for (int t = 0; t < NT; t++){
        if (t < NT - 1){
            cp_stage(smb + (((t + 1) & 1) ? OF_S1 : OF_S0), gK4 + (size_t)(t + 1) * 2048, tid);
            asm volatile("cp.async.commit_group;");
        }

        // ---- dropout masks (overlap cp.async latency) ----
        u32 km0 = 0, km1 = 0;
        {
            u32 base0 = ((u32)(b * Mm + mrow0 + r0 + gID)) * 2048u + (u32)(t * 64 + 2 * tig);
            u32 base1 = base0 + 8u * 2048u;
            #pragma unroll 1
            for (int jj = 0; jj < 8; jj++){
                u32 c0 = base0 + (u32)(jj * 8);
                u32 c1 = base1 + (u32)(jj * 8);
                u32 e00 = tf_keep(c0), e01 = tf_keep(c0 + 1u);
                u32 e10 = tf_keep(c1), e11 = tf_keep(c1 + 1u);
                km0 |= (e00 << (2 * jj)) | (e01 << (2 * jj + 1));
                km1 |= (e10 << (2 * jj)) | (e11 << (2 * jj + 1));
            }
        }

        if (t < NT - 1) { asm volatile("cp.async.wait_group 1;" ::: "memory"); }
        else            { asm volatile("cp.async.wait_group 0;" ::: "memory"); }
        __syncthreads();   // staging[t] ready; prev-tile K readers done

        // ---- convert K tile fp32 -> bf16 hi/lo (swizzled) ----
        {
            int krow = tid >> 2, seg = tid & 3;
            const char* stg = sm + ((t & 1) ? OF_S1 : OF_S0);
            char* khp = sm + OF_KH;
            char* klp = sm + OF_KL;
            #pragma unroll
            for (int j = 0; j < 8; j++){
                int rc = ((seg * 8 + j) ^ (krow & 7));
                float4 v = *(const float4*)(stg + krow * 512 + rc * 16);
                int d0 = seg * 32 + 4 * j;
                int cb = 2 * d0;
                int a0 = krow * 256 + (((cb >> 4) ^ (krow & 7)) << 4) + (cb & 15);
                u32 h2, l2;
                split_pair(v.x, v.y, h2, l2);
                *(u32*)(khp + a0) = h2; *(u32*)(klp + a0) = l2;
                split_pair(v.z, v.w, h2, l2);
                *(u32*)(khp + a0 + 4) = h2; *(u32*)(klp + a0 + 4) = l2;
            }
        }
        __syncthreads();

        // ---- QK: S(16x64) = Qh*Kh + Qh*Kl + Ql*Kh ----
        float s[8][4];
        #pragma unroll
        for (int i = 0; i < 8; i++){ s[i][0]=s[i][1]=s[i][2]=s[i][3]=0.f; }

        #pragma unroll
        for (int k = 0; k < 8; k++){
            int dby = k * 32;
            u32 ah[4], al[4];
            ldsm4(ah, swa(QH, rA + r0, dby + cA));
            ldsm4(al, swa(QL, rA + r0, dby + cA));
            #pragma unroll
            for (int nb = 0; nb < 4; nb++){
                u32 bh[4], bl[4];
                ldsm4(bh, swa(KH, nb * 16 + rBq, dby + cBq));
                ldsm4(bl, swa(KL, nb * 16 + rBq, dby + cBq));
                mmabf(s[2*nb],   ah, bh[0], bh[1]);
                mmabf(s[2*nb],   ah, bl[0], bl[1]);
                mmabf(s[2*nb],   al, bh[0], bh[1]);
                mmabf(s[2*nb+1], ah, bh[2], bh[3]);
                mmabf(s[2*nb+1], ah, bl[2], bl[3]);
                mmabf(s[2*nb+1], al, bh[2], bh[3]);
            }
        }

        // ---- softmax + dropout; build P fragments in registers (FA2 trick) ----
        u32 ph[4][4], pl[4][4];
        #pragma unroll
        for (int nb = 0; nb < 4; nb++){
            #pragma unroll
            for (int ng = 0; ng < 2; ng++){
                float* c = s[2*nb + ng];
                float p0 = ex2f(c[0] * C2);
                float p1 = ex2f(c[1] * C2);
                float p2 = ex2f(c[2] * C2);
                float p3 = ex2f(c[3] * C2);
                lsum0 += p0 + p1;
                lsum1 += p2 + p3;
                int jj = nb * 2 + ng;
                float q0 = ((km0 >> (2*jj)) & 1u)     ? p0 * INV_KEEP : 0.f;
                float q1 = ((km0 >> (2*jj+1)) & 1u)   ? p1 * INV_KEEP : 0.f;
                float q2 = ((km1 >> (2*jj)) & 1u)     ? p2 * INV_KEEP : 0.f;
                float q3 = ((km1 >> (2*jj+1)) & 1u)   ? p3 * INV_KEEP : 0.f;
                u32 h01, l01, h23, l23;
                split_pair(q0, q1, h01, l01);
                split_pair(q2, q3, h23, l23);
                ph[nb][2*ng]   = h01;  pl[nb][2*ng]   = l01;
                ph[nb][2*ng+1] = h23;  pl[nb][2*ng+1] = l23;
            }
        }

        // ---- PV: O(16x128) += Ph*Vh + Ph*Vl + Pl*Vh   (V = K tile, trans) ----
        #pragma unroll
        for (int kk = 0; kk < 4; kk++){
            int n0 = kk * 16;
            #pragma unroll
            for (int dg = 0; dg < 8; dg++){
                int dby = dg * 32;
                u32 bh[4], bl[4];
                ldsm4t(bh, swa(KH, n0 + rA, dby + cA));
                ldsm4t(bl, swa(KL, n0 + rA, dby + cA));
                mmabf(o[2*dg],   ph[kk], bh[0], bh[1]);
                mmabf(o[2*dg],   ph[kk], bl[0], bl[1]);
                mmabf(o[2*dg],   pl[kk], bh[0], bh[1]);
                mmabf(o[2*dg+1], ph[kk], bh[2], bh[3]);
                mmabf(o[2*dg+1], ph[kk], bl[2], bl[3]);
                mmabf(o[2*dg+1], pl[kk], bh[2], bh[3]);
            }
        }
    }

    // ---- epilogue: reduce row sums over the 4-lane quad, write O/l ----
    lsum0 += __shfl_xor_sync(0xffffffffu, lsum0, 1);
    lsum0 += __shfl_xor_sync(0xffffffffu, lsum0, 2);
    lsum1 += __shfl_xor_sync(0xffffffffu, lsum1, 1);
    lsum1 += __shfl_xor_sync(0xffffffffu, lsum1, 2);
    float inv0 = 1.0f / lsum0;
    float inv1 = 1.0f / lsum1;

    float* g0 = out + ((size_t)b * Mm + mrow0 + r0 + gID) * Dd;
    float* g1 = g0 + 8 * Dd;
    #pragma unroll
    for (int i = 0; i < 16; i++){
        int d = i * 8 + 2 * tig;
        *(float2*)(g0 + d) = make_float2(o[i][0] * inv0, o[i][1] * inv0);
        *(float2*)(g1 + d) = make_float2(o[i][2] * inv1, o[i][3] * inv1);
    }
}

extern "C" void kernel_launch(void* const* d_in, const int* in_sizes, int n_in,
                              void* d_out, int out_size)
{
    const float* x1 = (const float*)d_in[0];
    const float* x2 = (const float*)d_in[1];
    float* out = (float*)d_out;

    cudaFuncSetAttribute(attn_hmma, cudaFuncAttributeMaxDynamicSharedMemorySize, SMEM_TOTAL);
    dim3 grid(Mm / BM, Bb);
    attn_hmma<<<grid, TPB, SMEM_TOTAL>>>(x1, x2, out);
}